// round 17
// baseline (speedup 1.0000x reference)
#include <cuda_runtime.h>
#include <cstdint>

#define DINL __device__ __forceinline__

// Frag-packed tf32 weights: [pass 8][kw 3][kh 3][mf 4][lane 32][4 floats]
// (a0,a1,a2,a3 of mma.m16n8k8 packed contiguously per lane -> one LDG.128)
__device__ __align__(16) unsigned char g_wA[8 * 18432];

constexpr uint32_t XROW   = 1056;            // 264 floats per (kh,ci) row; 264%32==8 -> conflict-free
constexpr uint32_t XSLAB  = 24 * XROW;       // 25344 B per pass (3 kh x 8 ci)
constexpr uint32_t SX     = 0;               // X double buffer: 2 x 25344
constexpr uint32_t SBAR   = 2 * XSLAB;       // 50688
constexpr uint32_t SMEMSZ = SBAR + 16;       // XF0 XF1

// ---------------- ptx helpers ----------------
DINL uint32_t s2u(const void* p){uint32_t a;asm("{.reg .u64 t; cvta.to.shared.u64 t,%1; cvt.u32.u64 %0,t;}":"=r"(a):"l"(p));return a;}
DINL void bar_init(uint32_t a,uint32_t c){asm volatile("mbarrier.init.shared.b64 [%0],%1;"::"r"(a),"r"(c):"memory");}
DINL void bar_expect_tx(uint32_t a,uint32_t b){asm volatile("mbarrier.arrive.expect_tx.shared.b64 _,[%0],%1;"::"r"(a),"r"(b):"memory");}
DINL void bar_wait(uint32_t a,uint32_t ph){
  uint32_t done;
  asm volatile("{\n\t.reg .pred p;\n\t"
               "mbarrier.try_wait.parity.acquire.cta.shared::cta.b64 p,[%1],%2;\n\t"
               "selp.b32 %0,1,0,p;\n\t}"
               :"=r"(done):"r"(a),"r"(ph):"memory");
  if(!done){
    asm volatile("{\n\t.reg .pred P1;\n\t"
                 "WAIT_LOOP_%=:\n\t"
                 "mbarrier.try_wait.parity.acquire.cta.shared::cta.b64 P1,[%0],%1,0x989680;\n\t"
                 "@P1 bra.uni WAIT_DONE_%=;\n\t"
                 "bra.uni WAIT_LOOP_%=;\n\t"
                 "WAIT_DONE_%=:\n\t}"
                 ::"r"(a),"r"(ph):"memory");
  }
}
DINL void bulk_cp(uint32_t dst,const void* src,uint32_t bytes,uint32_t mbar){
  asm volatile("cp.async.bulk.shared::cluster.global.mbarrier::complete_tx::bytes [%0],[%1],%2,[%3];"
               ::"r"(dst),"l"(src),"r"(bytes),"r"(mbar):"memory");
}
DINL uint32_t lds32(uint32_t a){
  uint32_t r; asm volatile("ld.shared.b32 %0,[%1];":"=r"(r):"r"(a)); return r;
}
DINL void ldg128nc(uint32_t* r, const void* p){
  asm volatile("ld.global.nc.v4.b32 {%0,%1,%2,%3},[%4];"
               :"=r"(r[0]),"=r"(r[1]),"=r"(r[2]),"=r"(r[3]):"l"(p));
}
DINL void mma(float* c, const uint32_t* a, uint32_t b0, uint32_t b1){
  asm volatile("mma.sync.aligned.m16n8k8.row.col.f32.tf32.tf32.f32 "
               "{%0,%1,%2,%3},{%4,%5,%6,%7},{%8,%9},{%0,%1,%2,%3};"
               :"+f"(c[0]),"+f"(c[1]),"+f"(c[2]),"+f"(c[3])
               :"r"(a[0]),"r"(a[1]),"r"(a[2]),"r"(a[3]),"r"(b0),"r"(b1));
}
DINL uint32_t f2tf(float f){uint32_t u;asm("cvt.rna.tf32.f32 %0,%1;":"=r"(u):"f"(f));return u;}

// ---------------- weight prep: frag-pack + tf32 round ----------------
// blockIdx.x = pass*9 + kw*3 + kh ; 128 threads = mf*32 + lane
__global__ void prep_w(const float* __restrict__ wgt){
  int blk = blockIdx.x;
  int pass = blk / 9, rem = blk % 9, kw = rem / 3, kh = rem % 3;
  int t = threadIdx.x;
  int mf = t >> 5, lane = t & 31;
  int g = lane >> 2, tt = lane & 3;
  uint32_t u[4];
  #pragma unroll
  for (int j = 0; j < 4; j++){
    int co = mf*16 + g + (j & 1)*8;
    int ci = pass*8 + tt + (j >> 1)*4;
    u[j] = f2tf(wgt[co*576 + ci*9 + kh*3 + kw]);
  }
  uint4 q; q.x = u[0]; q.y = u[1]; q.z = u[2]; q.w = u[3];
  *(uint4*)(g_wA + (size_t)blk*2048 + (size_t)mf*512 + (size_t)lane*16) = q;
}

// ---------------- main kernel ----------------
// CTA = (h, b): OUT^T[co 64][px 256]. 8 warps, warp w covers px w*32..w*32+31.
__global__ __launch_bounds__(256, 3)
void conv_mma(const float* __restrict__ x,
              const float* __restrict__ bias,
              float* __restrict__ out)
{
  extern __shared__ __align__(128) unsigned char smem[];
  const uint32_t sb = s2u(smem);
  const int tid = threadIdx.x, wid = tid >> 5, lane = tid & 31;
  const int g = lane >> 2, tt = lane & 3;
  const int h = blockIdx.x, b = blockIdx.y;

  const uint32_t XFB = sb + SBAR;        // XF[0], XF[1]

  // zero the halo pads once (bytes 0..15 and 1040..1055 of every row, both buffers)
  if (tid < 96){
    int buf = tid / 48, rr = (tid % 48) >> 1, e = tid & 1;
    uint4 z = {0,0,0,0};
    *(uint4*)(smem + SX + (size_t)buf*XSLAB + (size_t)rr*XROW + (size_t)e*1040) = z;
  }
  if (tid == 0){
    bar_init(XFB, 1); bar_init(XFB + 8, 1);
  }
  __syncthreads();

  const int kh_lo = (h == 0) ? 1 : 0;
  const int kh_hi = (h == 255) ? 2 : 3;
  const uint32_t xtx = (uint32_t)(kh_hi - kh_lo) * 8192u;

  // X issuer (tid 0 only, never waits)
  auto issueX = [&](int p){
    uint32_t xb  = sb + SX + (uint32_t)(p & 1)*XSLAB;
    uint32_t bar = XFB + (uint32_t)(p & 1)*8u;
    bar_expect_tx(bar, xtx);
    for (int kh = kh_lo; kh < kh_hi; kh++)
      for (int ci = 0; ci < 8; ci++){
        const float* src = x + (((size_t)b*64 + p*8 + ci)*256 + (size_t)(h + kh - 1))*256;
        bulk_cp(xb + (uint32_t)(kh*8 + ci)*XROW + 16u, src, 1024u, bar);
      }
  };

  if (tid == 0){ issueX(0); issueX(1); }

  float acc[4][4][4];
  #pragma unroll
  for (int i = 0; i < 4; i++)
    #pragma unroll
    for (int j = 0; j < 4; j++)
      #pragma unroll
      for (int k = 0; k < 4; k++) acc[i][j][k] = 0.f;

  #pragma unroll 1
  for (int p = 0; p < 8; p++){
    // issue pass p+1: its buffer was consumed in pass p-1, which finished
    // before the __syncthreads we just passed -> race-free, no empty barriers.
    if (tid == 0 && p >= 1 && p <= 6) issueX(p + 1);

    bar_wait(XFB + (uint32_t)(p & 1)*8u, (uint32_t)((p >> 1) & 1));

    const uint32_t Xb = sb + SX + (uint32_t)(p & 1)*XSLAB;
    const unsigned char* Wp = g_wA + (size_t)p*18432 + (size_t)lane*16;

    #pragma unroll
    for (int kw = 0; kw < 3; kw++){
      #pragma unroll 1
      for (int kh = kh_lo; kh < kh_hi; kh++){
        // A fragments: 4 x LDG.128 from L1/L2-resident frag-packed weights
        const unsigned char* Aa = Wp + (size_t)(kw*3 + kh)*2048;
        uint32_t a[4][4];
        #pragma unroll
        for (int mf = 0; mf < 4; mf++) ldg128nc(a[mf], Aa + (size_t)mf*512);

        // B base: word = (kh*8 + tt)*264 + 4 + wid*32 + g + (kw-1)
        const uint32_t Baddr = Xb +
          ((uint32_t)(kh*8 + tt)*264u + 4u + (uint32_t)(wid*32) + (uint32_t)g
           + (uint32_t)kw - 1u)*4u;
        #pragma unroll
        for (int nf = 0; nf < 4; nf++){
          uint32_t b0 = lds32(Baddr + (uint32_t)nf*32u);
          uint32_t b1 = lds32(Baddr + (uint32_t)nf*32u + 4224u);  // +4 ci rows
          #pragma unroll
          for (int mf = 0; mf < 4; mf++)
            mma(acc[mf][nf], a[mf], b0, b1);
        }
      }
    }
    __syncthreads();   // pass handoff: all consumption of buf[p&1] complete
  }

  // ---- epilogue: OUT^T rows are coalesced ----
  #pragma unroll
  for (int mf = 0; mf < 4; mf++){
    int co = mf*16 + g;
    float bc0 = bias[co], bc8 = bias[co + 8];
    size_t base0 = (((size_t)b*64 + co)*256 + h)*256;
    #pragma unroll
    for (int nf = 0; nf < 4; nf++){
      int px = wid*32 + nf*8 + 2*tt;
      float2 v0, v1;
      v0.x = acc[mf][nf][0] + bc0; v0.y = acc[mf][nf][1] + bc0;
      v1.x = acc[mf][nf][2] + bc8; v1.y = acc[mf][nf][3] + bc8;
      *(float2*)(out + base0 + px) = v0;
      *(float2*)(out + base0 + (size_t)8*65536 + px) = v1;
    }
  }
}

// ---------------- launch ----------------
extern "C" void kernel_launch(void* const* d_in, const int* in_sizes, int n_in,
                              void* d_out, int out_size)
{
  (void)in_sizes; (void)n_in; (void)out_size;
  const float* x    = (const float*)d_in[0];
  const float* wgt  = (const float*)d_in[1];
  const float* bias = (const float*)d_in[2];
  float* out        = (float*)d_out;

  cudaFuncSetAttribute(conv_mma, cudaFuncAttributeMaxDynamicSharedMemorySize, SMEMSZ);

  prep_w<<<72, 128>>>(wgt);
  dim3 grid(256, 16);   // (h, b) = 4096 CTAs
  conv_mma<<<grid, 256, SMEMSZ>>>(x, bias, out);
}